// round 1
// baseline (speedup 1.0000x reference)
#include <cuda_runtime.h>
#include <math.h>

#define NMAX 200000
#define IN_DIM 1000
#define HD 256
#define ZD 32
#define NP 64
#define NC 8
#define NB 64

// ---------------- device scratch (no allocations allowed) ----------------
__device__ float g_h1[(size_t)NMAX * HD];   // after layer 1
__device__ float g_h2[(size_t)NMAX * HD];   // after layer 2
__device__ float g_bagsum[NB * NC];
__device__ float g_bagcnt[NB];

__device__ __forceinline__ float lrelu(float v) { return v > 0.0f ? v : 0.01f * v; }

// ---------------- zero the bag accumulators (graph replays!) -------------
__global__ void zero_accum_kernel() {
    int t = threadIdx.x;
    if (t < NB * NC) g_bagsum[t] = 0.0f;
    if (t < NB)      g_bagcnt[t] = 0.0f;
}

// ---------------- tiled fp32 GEMM:  C[n,m] = lrelu( sum_k A[n,k]*B[m,k] + bias[m] )
// A: [N,K] row-major, B: [M,K] row-major (i.e. C = A @ B^T), K % 8 == 0, M % 128 == 0.
__global__ __launch_bounds__(256, 2)
void gemm_nt_bias_lrelu(const float* __restrict__ A, const float* __restrict__ B,
                        const float* __restrict__ bias, float* __restrict__ C,
                        int N, int K, int M)
{
    __shared__ float As[8][128];
    __shared__ float Bs[8][128];

    const int tid = threadIdx.x;
    const int n0 = blockIdx.x * 128;
    const int m0 = blockIdx.y * 128;

    // loader mapping: 256 threads x float4 covers 128 rows x 8 k
    const int lr = tid >> 1;          // 0..127
    const int lc = (tid & 1) * 4;     // 0 or 4
    const bool a_valid = (n0 + lr) < N;

    const float* Ap = A + (size_t)(n0 + lr) * K + lc;
    const float* Bp = B + (size_t)(m0 + lr) * K + lc;

    // compute mapping: 16x16 threads, 8x8 micro-tile each
    const int tx = tid & 15;   // along m
    const int ty = tid >> 4;   // along n

    float acc[8][8];
#pragma unroll
    for (int i = 0; i < 8; i++)
#pragma unroll
        for (int j = 0; j < 8; j++) acc[i][j] = 0.0f;

    for (int k0 = 0; k0 < K; k0 += 8) {
        float4 av = make_float4(0.f, 0.f, 0.f, 0.f);
        if (a_valid) av = *reinterpret_cast<const float4*>(Ap);
        float4 bv = *reinterpret_cast<const float4*>(Bp);
        Ap += 8; Bp += 8;

        As[lc + 0][lr] = av.x; As[lc + 1][lr] = av.y;
        As[lc + 2][lr] = av.z; As[lc + 3][lr] = av.w;
        Bs[lc + 0][lr] = bv.x; Bs[lc + 1][lr] = bv.y;
        Bs[lc + 2][lr] = bv.z; Bs[lc + 3][lr] = bv.w;
        __syncthreads();

#pragma unroll
        for (int k = 0; k < 8; k++) {
            const float4* pa = reinterpret_cast<const float4*>(&As[k][ty * 8]);
            const float4* pb = reinterpret_cast<const float4*>(&Bs[k][tx * 8]);
            float4 a0 = pa[0], a1 = pa[1];
            float4 b0 = pb[0], b1 = pb[1];
            float ra[8] = {a0.x, a0.y, a0.z, a0.w, a1.x, a1.y, a1.z, a1.w};
            float rb[8] = {b0.x, b0.y, b0.z, b0.w, b1.x, b1.y, b1.z, b1.w};
#pragma unroll
            for (int i = 0; i < 8; i++)
#pragma unroll
                for (int j = 0; j < 8; j++)
                    acc[i][j] = fmaf(ra[i], rb[j], acc[i][j]);
        }
        __syncthreads();
    }

    // epilogue: bias + leaky relu
    float bs[8];
#pragma unroll
    for (int j = 0; j < 8; j++) bs[j] = bias[m0 + tx * 8 + j];

#pragma unroll
    for (int i = 0; i < 8; i++) {
        int r = n0 + ty * 8 + i;
        if (r >= N) continue;
        float* Crow = C + (size_t)r * M + m0 + tx * 8;
#pragma unroll
        for (int j = 0; j < 8; j += 4) {
            float4 v;
            v.x = lrelu(acc[i][j + 0] + bs[j + 0]);
            v.y = lrelu(acc[i][j + 1] + bs[j + 1]);
            v.z = lrelu(acc[i][j + 2] + bs[j + 2]);
            v.w = lrelu(acc[i][j + 3] + bs[j + 3]);
            *reinterpret_cast<float4*>(Crow + j) = v;
        }
    }
}

// ---------------- fused head: z = lrelu(h2 @ Wz^T + bz); dist->invdist->clf;
//                  block-local segment reduce, then global atomics -----------
__global__ __launch_bounds__(256)
void cell_head_kernel(const float* __restrict__ h2,
                      const int* __restrict__ seg,
                      const float* __restrict__ Wz, const float* __restrict__ bz,
                      const float* __restrict__ protos,
                      const float* __restrict__ Wclf,
                      int N)
{
    __shared__ float sWz[ZD * HD];      // 32 KB
    __shared__ float sProto[NP * ZD];   // 8 KB
    __shared__ float sPsq[NP];
    __shared__ float sWclf[NC * NP];    // 2 KB
    __shared__ float sBz[ZD];
    __shared__ float sBag[NB * NC];     // 2 KB
    __shared__ float sCnt[NB];

    const int tid = threadIdx.x;
    for (int i = tid; i < ZD * HD; i += 256) sWz[i] = Wz[i];
    for (int i = tid; i < NP * ZD; i += 256) sProto[i] = protos[i];
    for (int i = tid; i < NC * NP; i += 256) sWclf[i] = Wclf[i];
    if (tid < ZD) sBz[tid] = bz[tid];
    for (int i = tid; i < NB * NC; i += 256) sBag[i] = 0.0f;
    if (tid < NB) sCnt[tid] = 0.0f;
    __syncthreads();
    if (tid < NP) {
        float s = 0.0f;
#pragma unroll
        for (int j = 0; j < ZD; j++) { float p = sProto[tid * ZD + j]; s = fmaf(p, p, s); }
        sPsq[tid] = s;
    }
    __syncthreads();

    const int cell = blockIdx.x * 256 + tid;
    if (cell < N) {
        float z[ZD];
#pragma unroll
        for (int j = 0; j < ZD; j++) z[j] = sBz[j];

        const float4* hr = reinterpret_cast<const float4*>(h2 + (size_t)cell * HD);
#pragma unroll 4
        for (int k4 = 0; k4 < HD / 4; k4++) {
            float4 h4 = hr[k4];
#pragma unroll
            for (int j = 0; j < ZD; j++) {
                float4 w = *reinterpret_cast<const float4*>(&sWz[j * HD + k4 * 4]);
                z[j] = fmaf(h4.x, w.x, z[j]);
                z[j] = fmaf(h4.y, w.y, z[j]);
                z[j] = fmaf(h4.z, w.z, z[j]);
                z[j] = fmaf(h4.w, w.w, z[j]);
            }
        }
        float zsq = 0.0f;
#pragma unroll
        for (int j = 0; j < ZD; j++) { z[j] = lrelu(z[j]); zsq = fmaf(z[j], z[j], zsq); }

        float cl[NC];
#pragma unroll
        for (int c = 0; c < NC; c++) cl[c] = 0.0f;

#pragma unroll 2
        for (int p = 0; p < NP; p++) {
            const float4* pp = reinterpret_cast<const float4*>(&sProto[p * ZD]);
            float dot = 0.0f;
#pragma unroll
            for (int j4 = 0; j4 < ZD / 4; j4++) {
                float4 pv = pp[j4];
                dot = fmaf(z[j4 * 4 + 0], pv.x, dot);
                dot = fmaf(z[j4 * 4 + 1], pv.y, dot);
                dot = fmaf(z[j4 * 4 + 2], pv.z, dot);
                dot = fmaf(z[j4 * 4 + 3], pv.w, dot);
            }
            float d = zsq - 2.0f * dot + sPsq[p] + 0.5f;
            float inv = __fdividef(1.0f, d);
#pragma unroll
            for (int c = 0; c < NC; c++) cl[c] = fmaf(inv, sWclf[c * NP + p], cl[c]);
        }

        int b = seg[cell];
#pragma unroll
        for (int c = 0; c < NC; c++) atomicAdd(&sBag[b * NC + c], cl[c]);
        atomicAdd(&sCnt[b], 1.0f);
    }
    __syncthreads();

    for (int i = tid; i < NB * NC; i += 256)
        if (sBag[i] != 0.0f) atomicAdd(&g_bagsum[i], sBag[i]);
    if (tid < NB && sCnt[tid] != 0.0f) atomicAdd(&g_bagcnt[tid], sCnt[tid]);
}

// ---------------- finalize: mean pool, log_softmax, CE loss --------------
__global__ void finalize_kernel(const int* __restrict__ y, float* __restrict__ out,
                                int out_size)
{
    __shared__ float sLoss[NB];
    const int b = threadIdx.x;   // 64 threads
    float l[NC];
    float cnt = fmaxf(g_bagcnt[b], 1.0f);
    float inv = 1.0f / cnt;
    float m = -1e30f;
#pragma unroll
    for (int c = 0; c < NC; c++) {
        l[c] = g_bagsum[b * NC + c] * inv;
        m = fmaxf(m, l[c]);
    }
    float se = 0.0f;
#pragma unroll
    for (int c = 0; c < NC; c++) se += expf(l[c] - m);
    float lse = logf(se);
    int yc = y[b];
    sLoss[b] = -(l[yc] - m - lse);

    float* lo;
    bool write_loss;
    if (out_size == NB * NC) { lo = out; write_loss = false; }
    else                     { lo = out + 1; write_loss = true; }
    if (out_size >= NB * NC) {
#pragma unroll
        for (int c = 0; c < NC; c++) lo[b * NC + c] = l[c];
    }
    __syncthreads();
    if (b == 0 && write_loss) {
        float s = 0.0f;
        for (int i = 0; i < NB; i++) s += sLoss[i];
        out[0] = s / (float)NB;
    }
}

// ---------------- launch ----------------
extern "C" void kernel_launch(void* const* d_in, const int* in_sizes, int n_in,
                              void* d_out, int out_size)
{
    const float* x      = (const float*)d_in[0];
    const int*   y      = (const int*)  d_in[1];
    const int*   seg    = (const int*)  d_in[2];
    const float* W_i    = (const float*)d_in[3];
    const float* b_i    = (const float*)d_in[4];
    const float* W_h    = (const float*)d_in[5];
    const float* b_h    = (const float*)d_in[6];
    const float* W_z    = (const float*)d_in[7];
    const float* b_z    = (const float*)d_in[8];
    const float* protos = (const float*)d_in[9];
    const float* W_clf  = (const float*)d_in[10];

    const int N = in_sizes[0] / IN_DIM;   // 200000

    float *h1, *h2;
    cudaGetSymbolAddress((void**)&h1, g_h1);
    cudaGetSymbolAddress((void**)&h2, g_h2);

    zero_accum_kernel<<<1, 512>>>();

    dim3 grid1((N + 127) / 128, HD / 128);
    gemm_nt_bias_lrelu<<<grid1, 256>>>(x,  W_i, b_i, h1, N, IN_DIM, HD);
    gemm_nt_bias_lrelu<<<grid1, 256>>>(h1, W_h, b_h, h2, N, HD, HD);

    cell_head_kernel<<<(N + 255) / 256, 256>>>(h2, seg, W_z, b_z, protos, W_clf, N);

    finalize_kernel<<<1, NB>>>(y, (float*)d_out, out_size);
}

// round 3
// speedup vs baseline: 3.3001x; 3.3001x over previous
#include <cuda_runtime.h>
#include <cuda_fp16.h>
#include <cstdint>
#include <math.h>

#define IN_DIM 1000
#define KP1 1024
#define HD 256
#define ZD 32
#define NP 64
#define NC 8
#define NB 64
#define MBLK 1564
#define NPAD (MBLK * 128)        /* 200192 padded rows */

// ---------------- device scratch (no allocations allowed) ----------------
__device__ __align__(16) __half g_x16[(size_t)NPAD * KP1];   // x fp16, K padded
__device__ __align__(16) __half g_h1 [(size_t)NPAD * HD];    // layer-1 out fp16
__device__ __align__(16) float  g_z  [(size_t)NPAD * ZD];    // latent z fp32
__device__ __align__(16) __half g_w1p[512 * KP1];            // W_i hi/lo packed
__device__ __align__(16) __half g_w2p[512 * HD];             // W_h hi/lo packed
__device__ __align__(16) __half g_wzp[64 * HD];              // W_z hi/lo packed
__device__ float g_bagsum[NB * NC];
__device__ float g_bagcnt[NB];

__device__ __forceinline__ float lrelu(float v) { return v > 0.0f ? v : 0.01f * v; }

__device__ __forceinline__ uint32_t s2u(const void* p) {
    uint32_t a;
    asm("{ .reg .u64 t; cvta.to.shared.u64 t, %1; cvt.u32.u64 %0, t; }" : "=r"(a) : "l"(p));
    return a;
}
__device__ __forceinline__ void cpa16(uint32_t dst, const void* src) {
    asm volatile("cp.async.cg.shared.global [%0], [%1], 16;" :: "r"(dst), "l"(src) : "memory");
}
__device__ __forceinline__ void ldx4(uint32_t& r0, uint32_t& r1, uint32_t& r2, uint32_t& r3,
                                     uint32_t addr) {
    asm volatile("ldmatrix.sync.aligned.m8n8.x4.shared.b16 {%0,%1,%2,%3}, [%4];"
                 : "=r"(r0), "=r"(r1), "=r"(r2), "=r"(r3) : "r"(addr));
}
__device__ __forceinline__ void mma16816(float (&c)[4], const uint32_t (&a)[4],
                                         uint32_t b0, uint32_t b1) {
    asm volatile(
        "mma.sync.aligned.m16n8k16.row.col.f32.f16.f16.f32 "
        "{%0,%1,%2,%3}, {%4,%5,%6,%7}, {%8,%9}, {%0,%1,%2,%3};"
        : "+f"(c[0]), "+f"(c[1]), "+f"(c[2]), "+f"(c[3])
        : "r"(a[0]), "r"(a[1]), "r"(a[2]), "r"(a[3]), "r"(b0), "r"(b1));
}

// ---------------- smem layout (bytes) ----------------
#define ASTG 10240                      /* 128 rows * 80B */
#define BSTG 20480                      /* 256 rows * 80B */
#define OFF_A 0
#define OFF_B (3 * ASTG)                /* 30720 */
#define OFF_BIAS (OFF_B + 3 * BSTG)     /* 92160 */
#define OFF_BZ (OFF_BIAS + 1024)        /* 93184 */
#define SMEM1 (OFF_BZ + 128)            /* 93312 : MODE1 */
#define OFF_H2 SMEM1                    /* 128 rows * 528B = 67584 */
#define OFF_WZ (OFF_H2 + 67584)         /* 64 rows * 528B = 33792 */
#define SMEM2 (OFF_WZ + 33792)          /* 194688 : MODE2 */

// ---------------- small prep kernels ----------------
__global__ void zero_accum_kernel() {
    int t = threadIdx.x;
    if (t < NB * NC) g_bagsum[t] = 0.0f;
    if (t < NB)      g_bagcnt[t] = 0.0f;
}

__global__ void convert_x_kernel(const float* __restrict__ x, int N) {
    const int row = blockIdx.x;
    const int t = threadIdx.x;
    __half2 h0, h1;
    if (row < N && t * 4 < IN_DIM) {
        float4 v = *reinterpret_cast<const float4*>(x + (size_t)row * IN_DIM + t * 4);
        h0 = __floats2half2_rn(v.x, v.y);
        h1 = __floats2half2_rn(v.z, v.w);
    } else {
        h0 = __floats2half2_rn(0.f, 0.f);
        h1 = h0;
    }
    __half2* out = reinterpret_cast<__half2*>(g_x16 + (size_t)row * KP1 + t * 4);
    out[0] = h0; out[1] = h1;
}

// pack weight [M, K] fp32 -> [2M, Kp] fp16: rows 0..M-1 hi, M..2M-1 lo residual
__global__ void pack_w_kernel(const float* __restrict__ W, __half* __restrict__ out,
                              int K, int Kp, int M) {
    int idx = blockIdx.x * 256 + threadIdx.x;
    int r = idx / Kp, k = idx - r * Kp;
    if (r >= M) return;
    float w = (k < K) ? W[(size_t)r * K + k] : 0.0f;
    __half hi = __float2half_rn(w);
    __half lo = __float2half_rn(w - __half2float(hi));
    out[(size_t)r * Kp + k] = hi;
    out[(size_t)(r + M) * Kp + k] = lo;
}

// ---------------- warp-mma GEMM ----------------
// C = A[128 rows] @ (B_hi + B_lo)^T for one 128-col block, then:
// MODE 1: h1 = fp16(lrelu(C + bias)) -> global
// MODE 2: loop both col blocks into smem h2 tile; then z = lrelu(h2@Wz^T + bz) via mma
template<int KTOT, int MODE>
__global__ __launch_bounds__(256, MODE == 1 ? 2 : 1)
void gemm_kernel(const __half* __restrict__ A, const __half* __restrict__ Bp,
                 const float* __restrict__ bias, __half* __restrict__ h1out,
                 const __half* __restrict__ Wzp, const float* __restrict__ bz,
                 float* __restrict__ zout)
{
    extern __shared__ char smem[];
    const uint32_t su = s2u(smem);
    const int tid = threadIdx.x, lane = tid & 31, wid = tid >> 5;
    const int warp_m = wid & 3, warp_n = wid >> 2;

    float* s_bias = (float*)(smem + OFF_BIAS);
    s_bias[tid] = bias[tid];
    if (MODE == 2) {
        float* s_bz = (float*)(smem + OFF_BZ);
        if (tid < ZD) s_bz[tid] = bz[tid];
        for (int c = tid; c < 64 * 32; c += 256) {      // Wz packed -> padded smem
            int row = c >> 5, seg = c & 31;
            uint4 v = *reinterpret_cast<const uint4*>(Wzp + (size_t)row * HD + seg * 8);
            *reinterpret_cast<uint4*>(smem + OFF_WZ + row * 528 + seg * 16) = v;
        }
    }
    __syncthreads();

    const size_t rowbase = (size_t)blockIdx.x * 128;
    constexpr int NCH = KTOT / 32;

    // lane-derived ldmatrix offsets
    const int a_r = lane & 15, a_k = (lane >> 4) * 8;
    const int b_n = (lane & 7) + ((lane >> 4) << 3);
    const int b_k = ((lane >> 3) & 1) * 8;

    const int NCB = (MODE == 2) ? 2 : 1;
    for (int cb = 0; cb < NCB; cb++) {
        const int cbi = (MODE == 2) ? cb : blockIdx.y;

        float acc[2][8][4];
#pragma unroll
        for (int mt = 0; mt < 2; mt++)
#pragma unroll
            for (int nt = 0; nt < 8; nt++)
#pragma unroll
                for (int i = 0; i < 4; i++) acc[mt][nt][i] = 0.0f;

        auto load_chunk = [&](int c, int st) {
            const int k0 = c * 32;
            const uint32_t ab = su + OFF_A + st * ASTG;
            const uint32_t bb = su + OFF_B + st * BSTG;
#pragma unroll
            for (int i = 0; i < 2; i++) {               // A: 512 segs
                int s = tid + i * 256;
                int row = s >> 2, kseg = s & 3;
                cpa16(ab + row * 80 + kseg * 16,
                      A + (rowbase + row) * KTOT + k0 + kseg * 8);
            }
#pragma unroll
            for (int i = 0; i < 4; i++) {               // B hi/lo: 1024 segs
                int s = tid + i * 256;
                int row = s >> 2, kseg = s & 3;
                int srow = (row < 128) ? (cbi * 128 + row) : (256 + cbi * 128 + (row - 128));
                cpa16(bb + row * 80 + kseg * 16,
                      Bp + (size_t)srow * KTOT + k0 + kseg * 8);
            }
            asm volatile("cp.async.commit_group;" ::: "memory");
        };

        load_chunk(0, 0);
        if (NCH > 1) load_chunk(1, 1);
        if (NCH > 2) load_chunk(2, 2);

        for (int c = 0; c < NCH; c++) {
            if (c < NCH - 2)      asm volatile("cp.async.wait_group %0;" :: "n"(2) : "memory");
            else if (c == NCH - 2) asm volatile("cp.async.wait_group %0;" :: "n"(1) : "memory");
            else                   asm volatile("cp.async.wait_group %0;" :: "n"(0) : "memory");
            __syncthreads();

            const int st = c % 3;
            const uint32_t ab = su + OFF_A + st * ASTG;
            const uint32_t bb = su + OFF_B + st * BSTG;
#pragma unroll
            for (int s = 0; s < 2; s++) {
                uint32_t a[2][4];
#pragma unroll
                for (int mt = 0; mt < 2; mt++)
                    ldx4(a[mt][0], a[mt][1], a[mt][2], a[mt][3],
                         ab + (warp_m * 32 + mt * 16 + a_r) * 80 + (s * 16 + a_k) * 2);
                uint32_t b[4][4];
#pragma unroll
                for (int p = 0; p < 4; p++)
                    ldx4(b[p][0], b[p][1], b[p][2], b[p][3],
                         bb + (warp_n * 64 + p * 16 + b_n) * 80 + (s * 16 + b_k) * 2);
#pragma unroll
                for (int mt = 0; mt < 2; mt++)
#pragma unroll
                    for (int nt = 0; nt < 8; nt++)
                        mma16816(acc[mt][nt], a[mt], b[nt >> 1][(nt & 1) * 2],
                                 b[nt >> 1][(nt & 1) * 2 + 1]);
#pragma unroll
                for (int p = 0; p < 4; p++)             // lo rows at +128
                    ldx4(b[p][0], b[p][1], b[p][2], b[p][3],
                         bb + (128 + warp_n * 64 + p * 16 + b_n) * 80 + (s * 16 + b_k) * 2);
#pragma unroll
                for (int mt = 0; mt < 2; mt++)
#pragma unroll
                    for (int nt = 0; nt < 8; nt++)
                        mma16816(acc[mt][nt], a[mt], b[nt >> 1][(nt & 1) * 2],
                                 b[nt >> 1][(nt & 1) * 2 + 1]);
            }
            __syncthreads();
            if (c + 3 < NCH) load_chunk(c + 3, (c + 3) % 3);
        }

        // epilogue for this column block
#pragma unroll
        for (int mt = 0; mt < 2; mt++) {
#pragma unroll
            for (int nt = 0; nt < 8; nt++) {
                int col = cbi * 128 + warp_n * 64 + nt * 8 + (lane & 3) * 2;
                int r0 = warp_m * 32 + mt * 16 + (lane >> 2);
                float v0 = lrelu(acc[mt][nt][0] + s_bias[col]);
                float v1 = lrelu(acc[mt][nt][1] + s_bias[col + 1]);
                float v2 = lrelu(acc[mt][nt][2] + s_bias[col]);
                float v3 = lrelu(acc[mt][nt][3] + s_bias[col + 1]);
                if (MODE == 1) {
                    __half2* p0 = reinterpret_cast<__half2*>(h1out + (rowbase + r0) * HD + col);
                    __half2* p1 = reinterpret_cast<__half2*>(h1out + (rowbase + r0 + 8) * HD + col);
                    *p0 = __floats2half2_rn(v0, v1);
                    *p1 = __floats2half2_rn(v2, v3);
                } else {
                    *reinterpret_cast<__half2*>(smem + OFF_H2 + r0 * 528 + col * 2) =
                        __floats2half2_rn(v0, v1);
                    *reinterpret_cast<__half2*>(smem + OFF_H2 + (r0 + 8) * 528 + col * 2) =
                        __floats2half2_rn(v2, v3);
                }
            }
        }
        if (MODE == 2) __syncthreads();
    }

    if (MODE == 2) {
        // z = lrelu(h2 @ Wz^T + bz)  via mma on the smem h2 tile
        const float* s_bz = (const float*)(smem + OFF_BZ);
        float zacc[4][4];
#pragma unroll
        for (int nt = 0; nt < 4; nt++)
#pragma unroll
            for (int i = 0; i < 4; i++) zacc[nt][i] = 0.0f;

        const uint32_t h2b = su + OFF_H2;
        const uint32_t wzb = su + OFF_WZ;
        const int arow = wid * 16 + a_r;
#pragma unroll 4
        for (int s = 0; s < 16; s++) {                  // K = 256
            uint32_t a[4];
            ldx4(a[0], a[1], a[2], a[3], h2b + arow * 528 + (s * 16 + a_k) * 2);
            uint32_t b[2][4];
#pragma unroll
            for (int p = 0; p < 2; p++)
                ldx4(b[p][0], b[p][1], b[p][2], b[p][3],
                     wzb + (p * 16 + b_n) * 528 + (s * 16 + b_k) * 2);
#pragma unroll
            for (int nt = 0; nt < 4; nt++)
                mma16816(zacc[nt], a, b[nt >> 1][(nt & 1) * 2], b[nt >> 1][(nt & 1) * 2 + 1]);
#pragma unroll
            for (int p = 0; p < 2; p++)                 // lo rows at +32
                ldx4(b[p][0], b[p][1], b[p][2], b[p][3],
                     wzb + (32 + p * 16 + b_n) * 528 + (s * 16 + b_k) * 2);
#pragma unroll
            for (int nt = 0; nt < 4; nt++)
                mma16816(zacc[nt], a, b[nt >> 1][(nt & 1) * 2], b[nt >> 1][(nt & 1) * 2 + 1]);
        }
#pragma unroll
        for (int nt = 0; nt < 4; nt++) {
            int col = nt * 8 + (lane & 3) * 2;
            int r0 = wid * 16 + (lane >> 2);
            float2 v0, v1;
            v0.x = lrelu(zacc[nt][0] + s_bz[col]);
            v0.y = lrelu(zacc[nt][1] + s_bz[col + 1]);
            v1.x = lrelu(zacc[nt][2] + s_bz[col]);
            v1.y = lrelu(zacc[nt][3] + s_bz[col + 1]);
            *reinterpret_cast<float2*>(zout + (rowbase + r0) * ZD + col) = v0;
            *reinterpret_cast<float2*>(zout + (rowbase + r0 + 8) * ZD + col) = v1;
        }
    }
}

// ---------------- head: distances -> inv -> classifier -> segment reduce ----------------
__global__ __launch_bounds__(256)
void head_kernel(const float* __restrict__ zin, const int* __restrict__ seg,
                 const float* __restrict__ protos, const float* __restrict__ Wclf, int N)
{
    __shared__ float sProto[NP * ZD];
    __shared__ float sPsq[NP];
    __shared__ float sWclf[NC * NP];
    __shared__ float sBag[NB * NC];
    __shared__ float sCnt[NB];

    const int tid = threadIdx.x;
    for (int i = tid; i < NP * ZD; i += 256) sProto[i] = protos[i];
    for (int i = tid; i < NC * NP; i += 256) sWclf[i] = Wclf[i];
    for (int i = tid; i < NB * NC; i += 256) sBag[i] = 0.0f;
    if (tid < NB) sCnt[tid] = 0.0f;
    __syncthreads();
    if (tid < NP) {
        float s = 0.0f;
#pragma unroll
        for (int j = 0; j < ZD; j++) { float p = sProto[tid * ZD + j]; s = fmaf(p, p, s); }
        sPsq[tid] = s;
    }
    __syncthreads();

    const int cell = blockIdx.x * 256 + tid;
    if (cell < N) {
        float z[ZD];
        const float4* zr = reinterpret_cast<const float4*>(zin + (size_t)cell * ZD);
#pragma unroll
        for (int j4 = 0; j4 < ZD / 4; j4++) {
            float4 v = zr[j4];
            z[j4 * 4 + 0] = v.x; z[j4 * 4 + 1] = v.y;
            z[j4 * 4 + 2] = v.z; z[j4 * 4 + 3] = v.w;
        }
        float zsq = 0.0f;
#pragma unroll
        for (int j = 0; j < ZD; j++) zsq = fmaf(z[j], z[j], zsq);

        float cl[NC];
#pragma unroll
        for (int c = 0; c < NC; c++) cl[c] = 0.0f;

#pragma unroll 2
        for (int p = 0; p < NP; p++) {
            const float4* pp = reinterpret_cast<const float4*>(&sProto[p * ZD]);
            float dot = 0.0f;
#pragma unroll
            for (int j4 = 0; j4 < ZD / 4; j4++) {
                float4 pv = pp[j4];
                dot = fmaf(z[j4 * 4 + 0], pv.x, dot);
                dot = fmaf(z[j4 * 4 + 1], pv.y, dot);
                dot = fmaf(z[j4 * 4 + 2], pv.z, dot);
                dot = fmaf(z[j4 * 4 + 3], pv.w, dot);
            }
            float d = zsq - 2.0f * dot + sPsq[p] + 0.5f;
            float inv = __fdividef(1.0f, d);
#pragma unroll
            for (int c = 0; c < NC; c++) cl[c] = fmaf(inv, sWclf[c * NP + p], cl[c]);
        }
        int b = seg[cell];
#pragma unroll
        for (int c = 0; c < NC; c++) atomicAdd(&sBag[b * NC + c], cl[c]);
        atomicAdd(&sCnt[b], 1.0f);
    }
    __syncthreads();
    for (int i = tid; i < NB * NC; i += 256)
        if (sBag[i] != 0.0f) atomicAdd(&g_bagsum[i], sBag[i]);
    if (tid < NB && sCnt[tid] != 0.0f) atomicAdd(&g_bagcnt[tid], sCnt[tid]);
}

// ---------------- finalize ----------------
__global__ void finalize_kernel(const int* __restrict__ y, float* __restrict__ out,
                                int out_size)
{
    __shared__ float sLoss[NB];
    const int b = threadIdx.x;
    float l[NC];
    float cnt = fmaxf(g_bagcnt[b], 1.0f);
    float inv = 1.0f / cnt;
    float m = -1e30f;
#pragma unroll
    for (int c = 0; c < NC; c++) { l[c] = g_bagsum[b * NC + c] * inv; m = fmaxf(m, l[c]); }
    float se = 0.0f;
#pragma unroll
    for (int c = 0; c < NC; c++) se += expf(l[c] - m);
    float lse = logf(se);
    int yc = y[b];
    sLoss[b] = -(l[yc] - m - lse);

    float* lo;
    bool write_loss;
    if (out_size == NB * NC) { lo = out; write_loss = false; }
    else                     { lo = out + 1; write_loss = true; }
    if (out_size >= NB * NC) {
#pragma unroll
        for (int c = 0; c < NC; c++) lo[b * NC + c] = l[c];
    }
    __syncthreads();
    if (b == 0 && write_loss) {
        float s = 0.0f;
        for (int i = 0; i < NB; i++) s += sLoss[i];
        out[0] = s / (float)NB;
    }
}

// ---------------- launch ----------------
extern "C" void kernel_launch(void* const* d_in, const int* in_sizes, int n_in,
                              void* d_out, int out_size)
{
    const float* x      = (const float*)d_in[0];
    const int*   y      = (const int*)  d_in[1];
    const int*   seg    = (const int*)  d_in[2];
    const float* W_i    = (const float*)d_in[3];
    const float* b_i    = (const float*)d_in[4];
    const float* W_h    = (const float*)d_in[5];
    const float* b_h    = (const float*)d_in[6];
    const float* W_z    = (const float*)d_in[7];
    const float* b_z    = (const float*)d_in[8];
    const float* protos = (const float*)d_in[9];
    const float* W_clf  = (const float*)d_in[10];

    const int N = in_sizes[0] / IN_DIM;

    __half *x16, *h1, *w1p, *w2p, *wzp;
    float* z;
    cudaGetSymbolAddress((void**)&x16, g_x16);
    cudaGetSymbolAddress((void**)&h1,  g_h1);
    cudaGetSymbolAddress((void**)&z,   g_z);
    cudaGetSymbolAddress((void**)&w1p, g_w1p);
    cudaGetSymbolAddress((void**)&w2p, g_w2p);
    cudaGetSymbolAddress((void**)&wzp, g_wzp);

    cudaFuncSetAttribute(gemm_kernel<KP1, 1>, cudaFuncAttributeMaxDynamicSharedMemorySize, SMEM1);
    cudaFuncSetAttribute(gemm_kernel<HD, 2>,  cudaFuncAttributeMaxDynamicSharedMemorySize, SMEM2);

    zero_accum_kernel<<<1, 512>>>();
    convert_x_kernel<<<NPAD, 256>>>(x, N);
    pack_w_kernel<<<(256 * KP1) / 256, 256>>>(W_i, w1p, IN_DIM, KP1, 256);
    pack_w_kernel<<<(256 * HD)  / 256, 256>>>(W_h, w2p, HD, HD, 256);
    pack_w_kernel<<<(ZD * HD)   / 256, 256>>>(W_z, wzp, HD, HD, ZD);

    dim3 grid1(MBLK, 2);
    gemm_kernel<KP1, 1><<<grid1, 256, SMEM1>>>(x16, w1p, b_i, h1, nullptr, nullptr, nullptr);
    gemm_kernel<HD, 2><<<MBLK, 256, SMEM2>>>(h1, w2p, b_h, nullptr, wzp, b_z, z);

    head_kernel<<<(N + 255) / 256, 256>>>(z, seg, protos, W_clf, N);
    finalize_kernel<<<1, NB>>>(y, (float*)d_out, out_size);
}

// round 4
// speedup vs baseline: 3.6487x; 1.1056x over previous
#include <cuda_runtime.h>
#include <cuda_fp16.h>
#include <cstdint>
#include <math.h>

#define IN_DIM 1000
#define KP1 1024
#define HD 256
#define ZD 32
#define NP 64
#define NC 8
#define NB 64
#define MBLK 1564
#define NPAD (MBLK * 128)        /* 200192 padded rows */

// ---------------- device scratch (no allocations allowed) ----------------
__device__ __align__(16) __half g_h1 [(size_t)NPAD * HD];    // layer-1 out fp16
__device__ __align__(16) float  g_z  [(size_t)NPAD * ZD];    // latent z fp32
__device__ __align__(16) __half g_w1p[512 * KP1];            // W_i hi/lo packed
__device__ __align__(16) __half g_w2p[512 * HD];             // W_h hi/lo packed
__device__ __align__(16) __half g_wzp[64 * HD];              // W_z hi/lo packed
__device__ float g_bagsum[NB * NC];
__device__ float g_bagcnt[NB];

__device__ __forceinline__ float lrelu(float v) { return v > 0.0f ? v : 0.01f * v; }

__device__ __forceinline__ uint32_t s2u(const void* p) {
    uint32_t a;
    asm("{ .reg .u64 t; cvta.to.shared.u64 t, %1; cvt.u32.u64 %0, t; }" : "=r"(a) : "l"(p));
    return a;
}
__device__ __forceinline__ void cpa16(uint32_t dst, const void* src) {
    asm volatile("cp.async.cg.shared.global [%0], [%1], 16;" :: "r"(dst), "l"(src) : "memory");
}
__device__ __forceinline__ void ldx4(uint32_t& r0, uint32_t& r1, uint32_t& r2, uint32_t& r3,
                                     uint32_t addr) {
    asm volatile("ldmatrix.sync.aligned.m8n8.x4.shared.b16 {%0,%1,%2,%3}, [%4];"
                 : "=r"(r0), "=r"(r1), "=r"(r2), "=r"(r3) : "r"(addr));
}
__device__ __forceinline__ void mma16816(float (&c)[4], const uint32_t (&a)[4],
                                         uint32_t b0, uint32_t b1) {
    asm volatile(
        "mma.sync.aligned.m16n8k16.row.col.f32.f16.f16.f32 "
        "{%0,%1,%2,%3}, {%4,%5,%6,%7}, {%8,%9}, {%0,%1,%2,%3};"
        : "+f"(c[0]), "+f"(c[1]), "+f"(c[2]), "+f"(c[3])
        : "r"(a[0]), "r"(a[1]), "r"(a[2]), "r"(a[3]), "r"(b0), "r"(b1));
}

// ---------------- small prep kernels ----------------
__global__ void zero_accum_kernel() {
    int t = threadIdx.x;
    if (t < NB * NC) g_bagsum[t] = 0.0f;
    if (t < NB)      g_bagcnt[t] = 0.0f;
}

// pack weight [M, K] fp32 -> [2M, Kp] fp16: rows 0..M-1 hi, M..2M-1 lo residual
__global__ void pack_w_kernel(const float* __restrict__ W, __half* __restrict__ out,
                              int K, int Kp, int M) {
    int idx = blockIdx.x * 256 + threadIdx.x;
    int r = idx / Kp, k = idx - r * Kp;
    if (r >= M) return;
    float w = (k < K) ? W[(size_t)r * K + k] : 0.0f;
    __half hi = __float2half_rn(w);
    __half lo = __float2half_rn(w - __half2float(hi));
    out[(size_t)r * Kp + k] = hi;
    out[(size_t)(r + M) * Kp + k] = lo;
}

// =================== GEMM1: h1 = fp16(lrelu(x @ (W_hi+W_lo)^T + b)) ===================
// 512 threads, CTA tile 128 rows x 256 cols, K = 1024 (x fp32 converted inline).
#define G1_ASTG 10240                       /* 128 rows * 80B */
#define G1_BSTG 40960                       /* 512 rows * 80B */
#define G1_OFF_A 0
#define G1_OFF_B (2 * G1_ASTG)              /* 20480 */
#define G1_OFF_BIAS (G1_OFF_B + 4 * G1_BSTG)/* 184320 */
#define G1_SMEM (G1_OFF_BIAS + 1024)        /* 185344 */

__global__ __launch_bounds__(512, 1)
void gemm1_kernel(const float* __restrict__ X, const __half* __restrict__ Bp,
                  const float* __restrict__ bias, __half* __restrict__ h1out, int N)
{
    extern __shared__ char smem[];
    const uint32_t su = s2u(smem);
    const int tid = threadIdx.x, lane = tid & 31, wid = tid >> 5;
    const int warp_m = wid & 3, warp_n = wid >> 2;

    float* s_bias = (float*)(smem + G1_OFF_BIAS);
    if (tid < 256) s_bias[tid] = bias[tid];

    const size_t rowbase = (size_t)blockIdx.x * 128;
    const int arow = tid >> 2;              // 0..127
    const int akq  = (tid & 3) * 8;         // 0,8,16,24
    const bool rowok = (rowbase + arow) < (size_t)N;
    const float* xrow = X + (rowbase + arow) * IN_DIM;

    float4 ar0, ar1;
    auto ldgA = [&](int c) {
        int k = c * 32 + akq;
        ar0 = (rowok && k     < IN_DIM) ? *reinterpret_cast<const float4*>(xrow + k)
                                        : make_float4(0.f, 0.f, 0.f, 0.f);
        ar1 = (rowok && k + 4 < IN_DIM) ? *reinterpret_cast<const float4*>(xrow + k + 4)
                                        : make_float4(0.f, 0.f, 0.f, 0.f);
    };
    auto stsA = [&](int st) {
        __half2 h[4];
        h[0] = __floats2half2_rn(ar0.x, ar0.y); h[1] = __floats2half2_rn(ar0.z, ar0.w);
        h[2] = __floats2half2_rn(ar1.x, ar1.y); h[3] = __floats2half2_rn(ar1.z, ar1.w);
        *reinterpret_cast<uint4*>(smem + G1_OFF_A + st * G1_ASTG + arow * 80 + (tid & 3) * 16)
            = *reinterpret_cast<uint4*>(h);
    };
    auto cpB = [&](int c, int st) {
        const uint32_t bb = su + G1_OFF_B + st * G1_BSTG;
#pragma unroll
        for (int i = 0; i < 4; i++) {
            int s = tid + i * 512;
            int row = s >> 2, seg = s & 3;
            cpa16(bb + row * 80 + seg * 16, Bp + (size_t)row * KP1 + c * 32 + seg * 8);
        }
        asm volatile("cp.async.commit_group;" ::: "memory");
    };

    float acc[2][8][4];
#pragma unroll
    for (int mt = 0; mt < 2; mt++)
#pragma unroll
        for (int nt = 0; nt < 8; nt++)
#pragma unroll
            for (int i = 0; i < 4; i++) acc[mt][nt][i] = 0.0f;

    ldgA(0); stsA(0);
    ldgA(1);
    cpB(0, 0); cpB(1, 1); cpB(2, 2);

    const int a_r = lane & 15, a_k = (lane >> 4) * 8;
    const int b_n = (lane & 7) + ((lane >> 4) << 3);
    const int b_k = ((lane >> 3) & 1) * 8;

    constexpr int NCH = KP1 / 32;           // 32
    for (int c = 0; c < NCH; c++) {
        if (c < NCH - 2)       asm volatile("cp.async.wait_group 2;" ::: "memory");
        else if (c == NCH - 2) asm volatile("cp.async.wait_group 1;" ::: "memory");
        else                   asm volatile("cp.async.wait_group 0;" ::: "memory");
        __syncthreads();
        if (c + 3 < NCH) cpB(c + 3, (c + 3) & 3);
        if (c + 1 < NCH) stsA((c + 1) & 1);
        if (c + 2 < NCH) ldgA(c + 2);

        const uint32_t ab = su + G1_OFF_A + (c & 1) * G1_ASTG;
        const uint32_t bb = su + G1_OFF_B + (c & 3) * G1_BSTG;
#pragma unroll
        for (int s = 0; s < 2; s++) {
            uint32_t a[2][4];
#pragma unroll
            for (int mt = 0; mt < 2; mt++)
                ldx4(a[mt][0], a[mt][1], a[mt][2], a[mt][3],
                     ab + (warp_m * 32 + mt * 16 + a_r) * 80 + (s * 16 + a_k) * 2);
            uint32_t b[4][4];
#pragma unroll
            for (int p = 0; p < 4; p++)
                ldx4(b[p][0], b[p][1], b[p][2], b[p][3],
                     bb + (warp_n * 64 + p * 16 + b_n) * 80 + (s * 16 + b_k) * 2);
#pragma unroll
            for (int mt = 0; mt < 2; mt++)
#pragma unroll
                for (int nt = 0; nt < 8; nt++)
                    mma16816(acc[mt][nt], a[mt], b[nt >> 1][(nt & 1) * 2],
                             b[nt >> 1][(nt & 1) * 2 + 1]);
#pragma unroll
            for (int p = 0; p < 4; p++)         // lo rows at +256
                ldx4(b[p][0], b[p][1], b[p][2], b[p][3],
                     bb + (256 + warp_n * 64 + p * 16 + b_n) * 80 + (s * 16 + b_k) * 2);
#pragma unroll
            for (int mt = 0; mt < 2; mt++)
#pragma unroll
                for (int nt = 0; nt < 8; nt++)
                    mma16816(acc[mt][nt], a[mt], b[nt >> 1][(nt & 1) * 2],
                             b[nt >> 1][(nt & 1) * 2 + 1]);
        }
    }

    // epilogue: bias + lrelu -> fp16
#pragma unroll
    for (int mt = 0; mt < 2; mt++) {
#pragma unroll
        for (int nt = 0; nt < 8; nt++) {
            int col = warp_n * 64 + nt * 8 + (lane & 3) * 2;
            int r0 = warp_m * 32 + mt * 16 + (lane >> 2);
            float v0 = lrelu(acc[mt][nt][0] + s_bias[col]);
            float v1 = lrelu(acc[mt][nt][1] + s_bias[col + 1]);
            float v2 = lrelu(acc[mt][nt][2] + s_bias[col]);
            float v3 = lrelu(acc[mt][nt][3] + s_bias[col + 1]);
            *reinterpret_cast<__half2*>(h1out + (rowbase + r0) * HD + col) =
                __floats2half2_rn(v0, v1);
            *reinterpret_cast<__half2*>(h1out + (rowbase + r0 + 8) * HD + col) =
                __floats2half2_rn(v2, v3);
        }
    }
}

// =================== GEMM2 (fused z-projection), 256 threads ===================
#define ASTG 10240                      /* 128 rows * 80B */
#define BSTG 20480                      /* 256 rows * 80B */
#define OFF_A 0
#define OFF_B (3 * ASTG)                /* 30720 */
#define OFF_BIAS (OFF_B + 3 * BSTG)     /* 92160 */
#define OFF_BZ (OFF_BIAS + 1024)        /* 93184 */
#define OFF_H2 (OFF_BZ + 128)           /* 93312; 128 rows * 528B = 67584 */
#define OFF_WZ (OFF_H2 + 67584)         /* 64 rows * 528B = 33792 */
#define SMEM2 (OFF_WZ + 33792)          /* 194688 */

__global__ __launch_bounds__(256, 1)
void gemm2_kernel(const __half* __restrict__ A, const __half* __restrict__ Bp,
                  const float* __restrict__ bias,
                  const __half* __restrict__ Wzp, const float* __restrict__ bz,
                  float* __restrict__ zout)
{
    extern __shared__ char smem[];
    const uint32_t su = s2u(smem);
    const int tid = threadIdx.x, lane = tid & 31, wid = tid >> 5;
    const int warp_m = wid & 3, warp_n = wid >> 2;

    float* s_bias = (float*)(smem + OFF_BIAS);
    s_bias[tid] = bias[tid];
    {
        float* s_bz = (float*)(smem + OFF_BZ);
        if (tid < ZD) s_bz[tid] = bz[tid];
        for (int c = tid; c < 64 * 32; c += 256) {
            int row = c >> 5, seg = c & 31;
            uint4 v = *reinterpret_cast<const uint4*>(Wzp + (size_t)row * HD + seg * 8);
            *reinterpret_cast<uint4*>(smem + OFF_WZ + row * 528 + seg * 16) = v;
        }
    }
    __syncthreads();

    const size_t rowbase = (size_t)blockIdx.x * 128;
    constexpr int NCH = HD / 32;

    const int a_r = lane & 15, a_k = (lane >> 4) * 8;
    const int b_n = (lane & 7) + ((lane >> 4) << 3);
    const int b_k = ((lane >> 3) & 1) * 8;

    for (int cb = 0; cb < 2; cb++) {
        float acc[2][8][4];
#pragma unroll
        for (int mt = 0; mt < 2; mt++)
#pragma unroll
            for (int nt = 0; nt < 8; nt++)
#pragma unroll
                for (int i = 0; i < 4; i++) acc[mt][nt][i] = 0.0f;

        auto load_chunk = [&](int c, int st) {
            const int k0 = c * 32;
            const uint32_t ab = su + OFF_A + st * ASTG;
            const uint32_t bb = su + OFF_B + st * BSTG;
#pragma unroll
            for (int i = 0; i < 2; i++) {
                int s = tid + i * 256;
                int row = s >> 2, kseg = s & 3;
                cpa16(ab + row * 80 + kseg * 16,
                      A + (rowbase + row) * HD + k0 + kseg * 8);
            }
#pragma unroll
            for (int i = 0; i < 4; i++) {
                int s = tid + i * 256;
                int row = s >> 2, kseg = s & 3;
                int srow = (row < 128) ? (cb * 128 + row) : (256 + cb * 128 + (row - 128));
                cpa16(bb + row * 80 + kseg * 16,
                      Bp + (size_t)srow * HD + k0 + kseg * 8);
            }
            asm volatile("cp.async.commit_group;" ::: "memory");
        };

        load_chunk(0, 0);
        load_chunk(1, 1);
        load_chunk(2, 2);

        for (int c = 0; c < NCH; c++) {
            if (c < NCH - 2)       asm volatile("cp.async.wait_group 2;" ::: "memory");
            else if (c == NCH - 2) asm volatile("cp.async.wait_group 1;" ::: "memory");
            else                   asm volatile("cp.async.wait_group 0;" ::: "memory");
            __syncthreads();

            const int st = c % 3;
            const uint32_t ab = su + OFF_A + st * ASTG;
            const uint32_t bb = su + OFF_B + st * BSTG;
#pragma unroll
            for (int s = 0; s < 2; s++) {
                uint32_t a[2][4];
#pragma unroll
                for (int mt = 0; mt < 2; mt++)
                    ldx4(a[mt][0], a[mt][1], a[mt][2], a[mt][3],
                         ab + (warp_m * 32 + mt * 16 + a_r) * 80 + (s * 16 + a_k) * 2);
                uint32_t b[4][4];
#pragma unroll
                for (int p = 0; p < 4; p++)
                    ldx4(b[p][0], b[p][1], b[p][2], b[p][3],
                         bb + (warp_n * 64 + p * 16 + b_n) * 80 + (s * 16 + b_k) * 2);
#pragma unroll
                for (int mt = 0; mt < 2; mt++)
#pragma unroll
                    for (int nt = 0; nt < 8; nt++)
                        mma16816(acc[mt][nt], a[mt], b[nt >> 1][(nt & 1) * 2],
                                 b[nt >> 1][(nt & 1) * 2 + 1]);
#pragma unroll
                for (int p = 0; p < 4; p++)
                    ldx4(b[p][0], b[p][1], b[p][2], b[p][3],
                         bb + (128 + warp_n * 64 + p * 16 + b_n) * 80 + (s * 16 + b_k) * 2);
#pragma unroll
                for (int mt = 0; mt < 2; mt++)
#pragma unroll
                    for (int nt = 0; nt < 8; nt++)
                        mma16816(acc[mt][nt], a[mt], b[nt >> 1][(nt & 1) * 2],
                                 b[nt >> 1][(nt & 1) * 2 + 1]);
            }
            __syncthreads();
            if (c + 3 < NCH) load_chunk(c + 3, (c + 3) % 3);
        }

        // epilogue: h2 tile -> smem (fp16)
#pragma unroll
        for (int mt = 0; mt < 2; mt++) {
#pragma unroll
            for (int nt = 0; nt < 8; nt++) {
                int col = cb * 128 + warp_n * 64 + nt * 8 + (lane & 3) * 2;
                int r0 = warp_m * 32 + mt * 16 + (lane >> 2);
                float v0 = lrelu(acc[mt][nt][0] + s_bias[col]);
                float v1 = lrelu(acc[mt][nt][1] + s_bias[col + 1]);
                float v2 = lrelu(acc[mt][nt][2] + s_bias[col]);
                float v3 = lrelu(acc[mt][nt][3] + s_bias[col + 1]);
                *reinterpret_cast<__half2*>(smem + OFF_H2 + r0 * 528 + col * 2) =
                    __floats2half2_rn(v0, v1);
                *reinterpret_cast<__half2*>(smem + OFF_H2 + (r0 + 8) * 528 + col * 2) =
                    __floats2half2_rn(v2, v3);
            }
        }
        __syncthreads();
    }

    // z = lrelu(h2 @ Wz^T + bz)
    {
        const float* s_bz = (const float*)(smem + OFF_BZ);
        float zacc[4][4];
#pragma unroll
        for (int nt = 0; nt < 4; nt++)
#pragma unroll
            for (int i = 0; i < 4; i++) zacc[nt][i] = 0.0f;

        const uint32_t h2b = su + OFF_H2;
        const uint32_t wzb = su + OFF_WZ;
        const int arow = wid * 16 + a_r;
#pragma unroll 4
        for (int s = 0; s < 16; s++) {
            uint32_t a[4];
            ldx4(a[0], a[1], a[2], a[3], h2b + arow * 528 + (s * 16 + a_k) * 2);
            uint32_t b[2][4];
#pragma unroll
            for (int p = 0; p < 2; p++)
                ldx4(b[p][0], b[p][1], b[p][2], b[p][3],
                     wzb + (p * 16 + b_n) * 528 + (s * 16 + b_k) * 2);
#pragma unroll
            for (int nt = 0; nt < 4; nt++)
                mma16816(zacc[nt], a, b[nt >> 1][(nt & 1) * 2], b[nt >> 1][(nt & 1) * 2 + 1]);
#pragma unroll
            for (int p = 0; p < 2; p++)
                ldx4(b[p][0], b[p][1], b[p][2], b[p][3],
                     wzb + (32 + p * 16 + b_n) * 528 + (s * 16 + b_k) * 2);
#pragma unroll
            for (int nt = 0; nt < 4; nt++)
                mma16816(zacc[nt], a, b[nt >> 1][(nt & 1) * 2], b[nt >> 1][(nt & 1) * 2 + 1]);
        }
#pragma unroll
        for (int nt = 0; nt < 4; nt++) {
            int col = nt * 8 + (lane & 3) * 2;
            int r0 = wid * 16 + (lane >> 2);
            float2 v0, v1;
            v0.x = lrelu(zacc[nt][0] + s_bz[col]);
            v0.y = lrelu(zacc[nt][1] + s_bz[col + 1]);
            v1.x = lrelu(zacc[nt][2] + s_bz[col]);
            v1.y = lrelu(zacc[nt][3] + s_bz[col + 1]);
            *reinterpret_cast<float2*>(zout + (rowbase + r0) * ZD + col) = v0;
            *reinterpret_cast<float2*>(zout + (rowbase + r0 + 8) * ZD + col) = v1;
        }
    }
}

// ---------------- head: distances -> inv -> classifier -> segment reduce ----------------
__global__ __launch_bounds__(256)
void head_kernel(const float* __restrict__ zin, const int* __restrict__ seg,
                 const float* __restrict__ protos, const float* __restrict__ Wclf, int N)
{
    __shared__ float sProto[NP * ZD];
    __shared__ float sPsq[NP];
    __shared__ float sWclf[NC * NP];
    __shared__ float sBag[NB * NC];
    __shared__ float sCnt[NB];

    const int tid = threadIdx.x;
    for (int i = tid; i < NP * ZD; i += 256) sProto[i] = protos[i];
    for (int i = tid; i < NC * NP; i += 256) sWclf[i] = Wclf[i];
    for (int i = tid; i < NB * NC; i += 256) sBag[i] = 0.0f;
    if (tid < NB) sCnt[tid] = 0.0f;
    __syncthreads();
    if (tid < NP) {
        float s = 0.0f;
#pragma unroll
        for (int j = 0; j < ZD; j++) { float p = sProto[tid * ZD + j]; s = fmaf(p, p, s); }
        sPsq[tid] = s;
    }
    __syncthreads();

    const int cell = blockIdx.x * 256 + tid;
    if (cell < N) {
        float z[ZD];
        const float4* zr = reinterpret_cast<const float4*>(zin + (size_t)cell * ZD);
#pragma unroll
        for (int j4 = 0; j4 < ZD / 4; j4++) {
            float4 v = zr[j4];
            z[j4 * 4 + 0] = v.x; z[j4 * 4 + 1] = v.y;
            z[j4 * 4 + 2] = v.z; z[j4 * 4 + 3] = v.w;
        }
        float zsq = 0.0f;
#pragma unroll
        for (int j = 0; j < ZD; j++) zsq = fmaf(z[j], z[j], zsq);

        float cl[NC];
#pragma unroll
        for (int c = 0; c < NC; c++) cl[c] = 0.0f;

#pragma unroll 2
        for (int p = 0; p < NP; p++) {
            const float4* pp = reinterpret_cast<const float4*>(&sProto[p * ZD]);
            float dot = 0.0f;
#pragma unroll
            for (int j4 = 0; j4 < ZD / 4; j4++) {
                float4 pv = pp[j4];
                dot = fmaf(z[j4 * 4 + 0], pv.x, dot);
                dot = fmaf(z[j4 * 4 + 1], pv.y, dot);
                dot = fmaf(z[j4 * 4 + 2], pv.z, dot);
                dot = fmaf(z[j4 * 4 + 3], pv.w, dot);
            }
            float d = zsq - 2.0f * dot + sPsq[p] + 0.5f;
            float inv = __fdividef(1.0f, d);
#pragma unroll
            for (int c = 0; c < NC; c++) cl[c] = fmaf(inv, sWclf[c * NP + p], cl[c]);
        }
        int b = seg[cell];
#pragma unroll
        for (int c = 0; c < NC; c++) atomicAdd(&sBag[b * NC + c], cl[c]);
        atomicAdd(&sCnt[b], 1.0f);
    }
    __syncthreads();
    for (int i = tid; i < NB * NC; i += 256)
        if (sBag[i] != 0.0f) atomicAdd(&g_bagsum[i], sBag[i]);
    if (tid < NB && sCnt[tid] != 0.0f) atomicAdd(&g_bagcnt[tid], sCnt[tid]);
}

// ---------------- finalize ----------------
__global__ void finalize_kernel(const int* __restrict__ y, float* __restrict__ out,
                                int out_size)
{
    __shared__ float sLoss[NB];
    const int b = threadIdx.x;
    float l[NC];
    float cnt = fmaxf(g_bagcnt[b], 1.0f);
    float inv = 1.0f / cnt;
    float m = -1e30f;
#pragma unroll
    for (int c = 0; c < NC; c++) { l[c] = g_bagsum[b * NC + c] * inv; m = fmaxf(m, l[c]); }
    float se = 0.0f;
#pragma unroll
    for (int c = 0; c < NC; c++) se += expf(l[c] - m);
    float lse = logf(se);
    int yc = y[b];
    sLoss[b] = -(l[yc] - m - lse);

    float* lo;
    bool write_loss;
    if (out_size == NB * NC) { lo = out; write_loss = false; }
    else                     { lo = out + 1; write_loss = true; }
    if (out_size >= NB * NC) {
#pragma unroll
        for (int c = 0; c < NC; c++) lo[b * NC + c] = l[c];
    }
    __syncthreads();
    if (b == 0 && write_loss) {
        float s = 0.0f;
        for (int i = 0; i < NB; i++) s += sLoss[i];
        out[0] = s / (float)NB;
    }
}

// ---------------- launch ----------------
extern "C" void kernel_launch(void* const* d_in, const int* in_sizes, int n_in,
                              void* d_out, int out_size)
{
    const float* x      = (const float*)d_in[0];
    const int*   y      = (const int*)  d_in[1];
    const int*   seg    = (const int*)  d_in[2];
    const float* W_i    = (const float*)d_in[3];
    const float* b_i    = (const float*)d_in[4];
    const float* W_h    = (const float*)d_in[5];
    const float* b_h    = (const float*)d_in[6];
    const float* W_z    = (const float*)d_in[7];
    const float* b_z    = (const float*)d_in[8];
    const float* protos = (const float*)d_in[9];
    const float* W_clf  = (const float*)d_in[10];

    const int N = in_sizes[0] / IN_DIM;

    __half *h1, *w1p, *w2p, *wzp;
    float* z;
    cudaGetSymbolAddress((void**)&h1,  g_h1);
    cudaGetSymbolAddress((void**)&z,   g_z);
    cudaGetSymbolAddress((void**)&w1p, g_w1p);
    cudaGetSymbolAddress((void**)&w2p, g_w2p);
    cudaGetSymbolAddress((void**)&wzp, g_wzp);

    cudaFuncSetAttribute(gemm1_kernel, cudaFuncAttributeMaxDynamicSharedMemorySize, G1_SMEM);
    cudaFuncSetAttribute(gemm2_kernel, cudaFuncAttributeMaxDynamicSharedMemorySize, SMEM2);

    zero_accum_kernel<<<1, 512>>>();
    pack_w_kernel<<<(256 * KP1) / 256, 256>>>(W_i, w1p, IN_DIM, KP1, 256);
    pack_w_kernel<<<(256 * HD)  / 256, 256>>>(W_h, w2p, HD, HD, 256);
    pack_w_kernel<<<(ZD * HD)   / 256, 256>>>(W_z, wzp, HD, HD, ZD);

    gemm1_kernel<<<MBLK, 512, G1_SMEM>>>(x, w1p, b_i, h1, N);
    gemm2_kernel<<<MBLK, 256, SMEM2>>>(h1, w2p, b_h, wzp, b_z, z);

    head_kernel<<<(N + 255) / 256, 256>>>(z, seg, protos, W_clf, N);
    finalize_kernel<<<1, NB>>>(y, (float*)d_out, out_size);
}

// round 5
// speedup vs baseline: 5.5729x; 1.5274x over previous
#include <cuda_runtime.h>
#include <cuda_fp16.h>
#include <cstdint>
#include <math.h>

#define IN_DIM 1000
#define KP1 1024
#define HD 256
#define ZD 32
#define NP 64
#define NC 8
#define NB 64
#define MBLK 1564
#define NPAD (MBLK * 128)        /* 200192 padded rows */

// ---------------- device scratch (no allocations allowed) ----------------
__device__ __align__(16) __half g_h1 [(size_t)NPAD * HD];    // layer-1 out fp16
__device__ __align__(16) float  g_z  [(size_t)NPAD * ZD];    // latent z fp32
__device__ __align__(16) __half g_w1p[256 * KP1];            // W_i fp16
__device__ __align__(16) __half g_w2p[256 * HD];             // W_h fp16
__device__ __align__(16) __half g_wzp[32 * HD];              // W_z fp16
__device__ float g_bagsum[NB * NC];
__device__ float g_bagcnt[NB];

__device__ __forceinline__ float lrelu(float v) { return v > 0.0f ? v : 0.01f * v; }

__device__ __forceinline__ uint32_t s2u(const void* p) {
    uint32_t a;
    asm("{ .reg .u64 t; cvta.to.shared.u64 t, %1; cvt.u32.u64 %0, t; }" : "=r"(a) : "l"(p));
    return a;
}
__device__ __forceinline__ void cpa16(uint32_t dst, const void* src) {
    asm volatile("cp.async.cg.shared.global [%0], [%1], 16;" :: "r"(dst), "l"(src) : "memory");
}
__device__ __forceinline__ void ldx4(uint32_t& r0, uint32_t& r1, uint32_t& r2, uint32_t& r3,
                                     uint32_t addr) {
    asm volatile("ldmatrix.sync.aligned.m8n8.x4.shared.b16 {%0,%1,%2,%3}, [%4];"
                 : "=r"(r0), "=r"(r1), "=r"(r2), "=r"(r3) : "r"(addr));
}
__device__ __forceinline__ void mma16816(float (&c)[4], const uint32_t (&a)[4],
                                         uint32_t b0, uint32_t b1) {
    asm volatile(
        "mma.sync.aligned.m16n8k16.row.col.f32.f16.f16.f32 "
        "{%0,%1,%2,%3}, {%4,%5,%6,%7}, {%8,%9}, {%0,%1,%2,%3};"
        : "+f"(c[0]), "+f"(c[1]), "+f"(c[2]), "+f"(c[3])
        : "r"(a[0]), "r"(a[1]), "r"(a[2]), "r"(a[3]), "r"(b0), "r"(b1));
}

// ---------------- small prep kernels ----------------
__global__ void zero_accum_kernel() {
    int t = threadIdx.x;
    if (t < NB * NC) g_bagsum[t] = 0.0f;
    if (t < NB)      g_bagcnt[t] = 0.0f;
}

// pack weight [M, K] fp32 -> [M, Kp] fp16
__global__ void pack_w_kernel(const float* __restrict__ W, __half* __restrict__ out,
                              int K, int Kp, int M) {
    int idx = blockIdx.x * 256 + threadIdx.x;
    int r = idx / Kp, k = idx - r * Kp;
    if (r >= M) return;
    float w = (k < K) ? W[(size_t)r * K + k] : 0.0f;
    out[(size_t)r * Kp + k] = __float2half_rn(w);
}

// =================== GEMM1: h1 = fp16(lrelu(x @ W^T + b)) ===================
// 512 threads, CTA tile 128 rows x 256 cols, K = 1024 (x fp32 converted inline).
#define G1_ASTG 10240                       /* 128 rows * 80B */
#define G1_BSTG 20480                       /* 256 rows * 80B */
#define G1_OFF_A 0
#define G1_OFF_B (2 * G1_ASTG)              /* 20480 */
#define G1_OFF_BIAS (G1_OFF_B + 4 * G1_BSTG)/* 102400 */
#define G1_SMEM (G1_OFF_BIAS + 1024)        /* 103424 */

__global__ __launch_bounds__(512, 1)
void gemm1_kernel(const float* __restrict__ X, const __half* __restrict__ Bp,
                  const float* __restrict__ bias, __half* __restrict__ h1out, int N)
{
    extern __shared__ char smem[];
    const uint32_t su = s2u(smem);
    const int tid = threadIdx.x, lane = tid & 31, wid = tid >> 5;
    const int warp_m = wid & 3, warp_n = wid >> 2;

    float* s_bias = (float*)(smem + G1_OFF_BIAS);
    if (tid < 256) s_bias[tid] = bias[tid];

    const size_t rowbase = (size_t)blockIdx.x * 128;
    const int arow = tid >> 2;              // 0..127
    const int akq  = (tid & 3) * 8;         // 0,8,16,24
    const bool rowok = (rowbase + arow) < (size_t)N;
    const float* xrow = X + (rowbase + arow) * IN_DIM;

    float4 ar0, ar1;
    auto ldgA = [&](int c) {
        int k = c * 32 + akq;
        ar0 = (rowok && k     < IN_DIM) ? *reinterpret_cast<const float4*>(xrow + k)
                                        : make_float4(0.f, 0.f, 0.f, 0.f);
        ar1 = (rowok && k + 4 < IN_DIM) ? *reinterpret_cast<const float4*>(xrow + k + 4)
                                        : make_float4(0.f, 0.f, 0.f, 0.f);
    };
    auto stsA = [&](int st) {
        __half2 h[4];
        h[0] = __floats2half2_rn(ar0.x, ar0.y); h[1] = __floats2half2_rn(ar0.z, ar0.w);
        h[2] = __floats2half2_rn(ar1.x, ar1.y); h[3] = __floats2half2_rn(ar1.z, ar1.w);
        *reinterpret_cast<uint4*>(smem + G1_OFF_A + st * G1_ASTG + arow * 80 + (tid & 3) * 16)
            = *reinterpret_cast<uint4*>(h);
    };
    auto cpB = [&](int c, int st) {
        const uint32_t bb = su + G1_OFF_B + st * G1_BSTG;
#pragma unroll
        for (int i = 0; i < 2; i++) {
            int s = tid + i * 512;
            int row = s >> 2, seg = s & 3;
            cpa16(bb + row * 80 + seg * 16, Bp + (size_t)row * KP1 + c * 32 + seg * 8);
        }
        asm volatile("cp.async.commit_group;" ::: "memory");
    };

    float acc[2][8][4];
#pragma unroll
    for (int mt = 0; mt < 2; mt++)
#pragma unroll
        for (int nt = 0; nt < 8; nt++)
#pragma unroll
            for (int i = 0; i < 4; i++) acc[mt][nt][i] = 0.0f;

    ldgA(0); stsA(0);
    ldgA(1);
    cpB(0, 0); cpB(1, 1); cpB(2, 2);

    const int a_r = lane & 15, a_k = (lane >> 4) * 8;
    const int b_n = (lane & 7) + ((lane >> 4) << 3);
    const int b_k = ((lane >> 3) & 1) * 8;

    constexpr int NCH = KP1 / 32;           // 32
    for (int c = 0; c < NCH; c++) {
        if (c < NCH - 2)       asm volatile("cp.async.wait_group 2;" ::: "memory");
        else if (c == NCH - 2) asm volatile("cp.async.wait_group 1;" ::: "memory");
        else                   asm volatile("cp.async.wait_group 0;" ::: "memory");
        __syncthreads();
        if (c + 3 < NCH) cpB(c + 3, (c + 3) & 3);
        if (c + 1 < NCH) stsA((c + 1) & 1);
        if (c + 2 < NCH) ldgA(c + 2);

        const uint32_t ab = su + G1_OFF_A + (c & 1) * G1_ASTG;
        const uint32_t bb = su + G1_OFF_B + (c & 3) * G1_BSTG;
#pragma unroll
        for (int s = 0; s < 2; s++) {
            uint32_t a[2][4];
#pragma unroll
            for (int mt = 0; mt < 2; mt++)
                ldx4(a[mt][0], a[mt][1], a[mt][2], a[mt][3],
                     ab + (warp_m * 32 + mt * 16 + a_r) * 80 + (s * 16 + a_k) * 2);
            uint32_t b[4][4];
#pragma unroll
            for (int p = 0; p < 4; p++)
                ldx4(b[p][0], b[p][1], b[p][2], b[p][3],
                     bb + (warp_n * 64 + p * 16 + b_n) * 80 + (s * 16 + b_k) * 2);
#pragma unroll
            for (int mt = 0; mt < 2; mt++)
#pragma unroll
                for (int nt = 0; nt < 8; nt++)
                    mma16816(acc[mt][nt], a[mt], b[nt >> 1][(nt & 1) * 2],
                             b[nt >> 1][(nt & 1) * 2 + 1]);
        }
    }

    // epilogue: bias + lrelu -> fp16
#pragma unroll
    for (int mt = 0; mt < 2; mt++) {
#pragma unroll
        for (int nt = 0; nt < 8; nt++) {
            int col = warp_n * 64 + nt * 8 + (lane & 3) * 2;
            int r0 = warp_m * 32 + mt * 16 + (lane >> 2);
            float v0 = lrelu(acc[mt][nt][0] + s_bias[col]);
            float v1 = lrelu(acc[mt][nt][1] + s_bias[col + 1]);
            float v2 = lrelu(acc[mt][nt][2] + s_bias[col]);
            float v3 = lrelu(acc[mt][nt][3] + s_bias[col + 1]);
            *reinterpret_cast<__half2*>(h1out + (rowbase + r0) * HD + col) =
                __floats2half2_rn(v0, v1);
            *reinterpret_cast<__half2*>(h1out + (rowbase + r0 + 8) * HD + col) =
                __floats2half2_rn(v2, v3);
        }
    }
}

// =================== GEMM2 (fused z-projection), 512 threads, single K pass ===================
#define ASTG 10240                      /* 128 rows * 80B */
#define BSTG 20480                      /* 256 rows * 80B */
#define OFF_A 0
#define OFF_B (3 * ASTG)                /* 30720 */
#define OFF_BIAS (OFF_B + 3 * BSTG)     /* 92160 */
#define OFF_BZ (OFF_BIAS + 1024)        /* 93184 */
#define OFF_WZ (OFF_BZ + 128)           /* 93312; 32 rows * 528B = 16896 */
#define OFF_H2 (OFF_WZ + 16896)         /* 110208; 128 rows * 528B = 67584 */
#define SMEM2 (OFF_H2 + 67584)          /* 177792 */

__global__ __launch_bounds__(512, 1)
void gemm2_kernel(const __half* __restrict__ A, const __half* __restrict__ Bp,
                  const float* __restrict__ bias,
                  const __half* __restrict__ Wzp, const float* __restrict__ bz,
                  float* __restrict__ zout)
{
    extern __shared__ char smem[];
    const uint32_t su = s2u(smem);
    const int tid = threadIdx.x, lane = tid & 31, wid = tid >> 5;
    const int warp_m = wid & 3, warp_n = wid >> 2;

    float* s_bias = (float*)(smem + OFF_BIAS);
    if (tid < 256) s_bias[tid] = bias[tid];
    {
        float* s_bz = (float*)(smem + OFF_BZ);
        if (tid < ZD) s_bz[tid] = bz[tid];
        for (int c = tid; c < 32 * 32; c += 512) {      // Wz 32 rows x 32 segs
            int row = c >> 5, seg = c & 31;
            uint4 v = *reinterpret_cast<const uint4*>(Wzp + (size_t)row * HD + seg * 8);
            *reinterpret_cast<uint4*>(smem + OFF_WZ + row * 528 + seg * 16) = v;
        }
    }

    const size_t rowbase = (size_t)blockIdx.x * 128;
    constexpr int NCH = HD / 32;        // 8

    const int a_r = lane & 15, a_k = (lane >> 4) * 8;
    const int b_n = (lane & 7) + ((lane >> 4) << 3);
    const int b_k = ((lane >> 3) & 1) * 8;

    float acc[2][8][4];
#pragma unroll
    for (int mt = 0; mt < 2; mt++)
#pragma unroll
        for (int nt = 0; nt < 8; nt++)
#pragma unroll
            for (int i = 0; i < 4; i++) acc[mt][nt][i] = 0.0f;

    auto load_chunk = [&](int c, int st) {
        const int k0 = c * 32;
        const uint32_t ab = su + OFF_A + st * ASTG;
        const uint32_t bb = su + OFF_B + st * BSTG;
        {   // A: 128 rows x 4 segs = 512 segs
            int row = tid >> 2, kseg = tid & 3;
            cpa16(ab + row * 80 + kseg * 16, A + (rowbase + row) * HD + k0 + kseg * 8);
        }
#pragma unroll
        for (int i = 0; i < 2; i++) {   // B: 256 rows x 4 segs = 1024 segs
            int s = tid + i * 512;
            int row = s >> 2, kseg = s & 3;
            cpa16(bb + row * 80 + kseg * 16, Bp + (size_t)row * HD + k0 + kseg * 8);
        }
        asm volatile("cp.async.commit_group;" ::: "memory");
    };

    load_chunk(0, 0);
    load_chunk(1, 1);
    load_chunk(2, 2);

    for (int c = 0; c < NCH; c++) {
        if (c < NCH - 2)       asm volatile("cp.async.wait_group 2;" ::: "memory");
        else if (c == NCH - 2) asm volatile("cp.async.wait_group 1;" ::: "memory");
        else                   asm volatile("cp.async.wait_group 0;" ::: "memory");
        __syncthreads();

        const int st = c % 3;
        const uint32_t ab = su + OFF_A + st * ASTG;
        const uint32_t bb = su + OFF_B + st * BSTG;
#pragma unroll
        for (int s = 0; s < 2; s++) {
            uint32_t a[2][4];
#pragma unroll
            for (int mt = 0; mt < 2; mt++)
                ldx4(a[mt][0], a[mt][1], a[mt][2], a[mt][3],
                     ab + (warp_m * 32 + mt * 16 + a_r) * 80 + (s * 16 + a_k) * 2);
            uint32_t b[4][4];
#pragma unroll
            for (int p = 0; p < 4; p++)
                ldx4(b[p][0], b[p][1], b[p][2], b[p][3],
                     bb + (warp_n * 64 + p * 16 + b_n) * 80 + (s * 16 + b_k) * 2);
#pragma unroll
            for (int mt = 0; mt < 2; mt++)
#pragma unroll
                for (int nt = 0; nt < 8; nt++)
                    mma16816(acc[mt][nt], a[mt], b[nt >> 1][(nt & 1) * 2],
                             b[nt >> 1][(nt & 1) * 2 + 1]);
        }
        __syncthreads();
        if (c + 3 < NCH) load_chunk(c + 3, (c + 3) % 3);
    }

    // epilogue: h2 tile -> smem (fp16)
#pragma unroll
    for (int mt = 0; mt < 2; mt++) {
#pragma unroll
        for (int nt = 0; nt < 8; nt++) {
            int col = warp_n * 64 + nt * 8 + (lane & 3) * 2;
            int r0 = warp_m * 32 + mt * 16 + (lane >> 2);
            float v0 = lrelu(acc[mt][nt][0] + s_bias[col]);
            float v1 = lrelu(acc[mt][nt][1] + s_bias[col + 1]);
            float v2 = lrelu(acc[mt][nt][2] + s_bias[col]);
            float v3 = lrelu(acc[mt][nt][3] + s_bias[col + 1]);
            *reinterpret_cast<__half2*>(smem + OFF_H2 + r0 * 528 + col * 2) =
                __floats2half2_rn(v0, v1);
            *reinterpret_cast<__half2*>(smem + OFF_H2 + (r0 + 8) * 528 + col * 2) =
                __floats2half2_rn(v2, v3);
        }
    }
    __syncthreads();

    // z = lrelu(h2 @ Wz^T + bz): warps 0..7, 16 rows each
    if (wid < 8) {
        const float* s_bz = (const float*)(smem + OFF_BZ);
        float zacc[4][4];
#pragma unroll
        for (int nt = 0; nt < 4; nt++)
#pragma unroll
            for (int i = 0; i < 4; i++) zacc[nt][i] = 0.0f;

        const uint32_t h2b = su + OFF_H2;
        const uint32_t wzb = su + OFF_WZ;
        const int arow = wid * 16 + a_r;
#pragma unroll 4
        for (int s = 0; s < 16; s++) {
            uint32_t a[4];
            ldx4(a[0], a[1], a[2], a[3], h2b + arow * 528 + (s * 16 + a_k) * 2);
            uint32_t b[2][4];
#pragma unroll
            for (int p = 0; p < 2; p++)
                ldx4(b[p][0], b[p][1], b[p][2], b[p][3],
                     wzb + (p * 16 + b_n) * 528 + (s * 16 + b_k) * 2);
#pragma unroll
            for (int nt = 0; nt < 4; nt++)
                mma16816(zacc[nt], a, b[nt >> 1][(nt & 1) * 2], b[nt >> 1][(nt & 1) * 2 + 1]);
        }
#pragma unroll
        for (int nt = 0; nt < 4; nt++) {
            int col = nt * 8 + (lane & 3) * 2;
            int r0 = wid * 16 + (lane >> 2);
            float2 v0, v1;
            v0.x = lrelu(zacc[nt][0] + s_bz[col]);
            v0.y = lrelu(zacc[nt][1] + s_bz[col + 1]);
            v1.x = lrelu(zacc[nt][2] + s_bz[col]);
            v1.y = lrelu(zacc[nt][3] + s_bz[col + 1]);
            *reinterpret_cast<float2*>(zout + (rowbase + r0) * ZD + col) = v0;
            *reinterpret_cast<float2*>(zout + (rowbase + r0 + 8) * ZD + col) = v1;
        }
    }
}

// ---------------- head: distances -> inv -> classifier -> segment reduce ----------------
__global__ __launch_bounds__(256)
void head_kernel(const float* __restrict__ zin, const int* __restrict__ seg,
                 const float* __restrict__ protos, const float* __restrict__ Wclf, int N)
{
    __shared__ float sProto[NP * ZD];
    __shared__ float sPsq[NP];
    __shared__ float sWclf[NC * NP];
    __shared__ float sBag[NB * NC];
    __shared__ float sCnt[NB];

    const int tid = threadIdx.x;
    for (int i = tid; i < NP * ZD; i += 256) sProto[i] = protos[i];
    for (int i = tid; i < NC * NP; i += 256) sWclf[i] = Wclf[i];
    for (int i = tid; i < NB * NC; i += 256) sBag[i] = 0.0f;
    if (tid < NB) sCnt[tid] = 0.0f;
    __syncthreads();
    if (tid < NP) {
        float s = 0.0f;
#pragma unroll
        for (int j = 0; j < ZD; j++) { float p = sProto[tid * ZD + j]; s = fmaf(p, p, s); }
        sPsq[tid] = s;
    }
    __syncthreads();

    const int cell = blockIdx.x * 256 + tid;
    if (cell < N) {
        float z[ZD];
        const float4* zr = reinterpret_cast<const float4*>(zin + (size_t)cell * ZD);
#pragma unroll
        for (int j4 = 0; j4 < ZD / 4; j4++) {
            float4 v = zr[j4];
            z[j4 * 4 + 0] = v.x; z[j4 * 4 + 1] = v.y;
            z[j4 * 4 + 2] = v.z; z[j4 * 4 + 3] = v.w;
        }
        float zsq = 0.0f;
#pragma unroll
        for (int j = 0; j < ZD; j++) zsq = fmaf(z[j], z[j], zsq);

        float cl[NC];
#pragma unroll
        for (int c = 0; c < NC; c++) cl[c] = 0.0f;

#pragma unroll 2
        for (int p = 0; p < NP; p++) {
            const float4* pp = reinterpret_cast<const float4*>(&sProto[p * ZD]);
            float dot = 0.0f;
#pragma unroll
            for (int j4 = 0; j4 < ZD / 4; j4++) {
                float4 pv = pp[j4];
                dot = fmaf(z[j4 * 4 + 0], pv.x, dot);
                dot = fmaf(z[j4 * 4 + 1], pv.y, dot);
                dot = fmaf(z[j4 * 4 + 2], pv.z, dot);
                dot = fmaf(z[j4 * 4 + 3], pv.w, dot);
            }
            float d = zsq - 2.0f * dot + sPsq[p] + 0.5f;
            float inv = __fdividef(1.0f, d);
#pragma unroll
            for (int c = 0; c < NC; c++) cl[c] = fmaf(inv, sWclf[c * NP + p], cl[c]);
        }
        int b = seg[cell];
#pragma unroll
        for (int c = 0; c < NC; c++) atomicAdd(&sBag[b * NC + c], cl[c]);
        atomicAdd(&sCnt[b], 1.0f);
    }
    __syncthreads();
    for (int i = tid; i < NB * NC; i += 256)
        if (sBag[i] != 0.0f) atomicAdd(&g_bagsum[i], sBag[i]);
    if (tid < NB && sCnt[tid] != 0.0f) atomicAdd(&g_bagcnt[tid], sCnt[tid]);
}

// ---------------- finalize ----------------
__global__ void finalize_kernel(const int* __restrict__ y, float* __restrict__ out,
                                int out_size)
{
    __shared__ float sLoss[NB];
    const int b = threadIdx.x;
    float l[NC];
    float cnt = fmaxf(g_bagcnt[b], 1.0f);
    float inv = 1.0f / cnt;
    float m = -1e30f;
#pragma unroll
    for (int c = 0; c < NC; c++) { l[c] = g_bagsum[b * NC + c] * inv; m = fmaxf(m, l[c]); }
    float se = 0.0f;
#pragma unroll
    for (int c = 0; c < NC; c++) se += expf(l[c] - m);
    float lse = logf(se);
    int yc = y[b];
    sLoss[b] = -(l[yc] - m - lse);

    float* lo;
    bool write_loss;
    if (out_size == NB * NC) { lo = out; write_loss = false; }
    else                     { lo = out + 1; write_loss = true; }
    if (out_size >= NB * NC) {
#pragma unroll
        for (int c = 0; c < NC; c++) lo[b * NC + c] = l[c];
    }
    __syncthreads();
    if (b == 0 && write_loss) {
        float s = 0.0f;
        for (int i = 0; i < NB; i++) s += sLoss[i];
        out[0] = s / (float)NB;
    }
}

// ---------------- launch ----------------
extern "C" void kernel_launch(void* const* d_in, const int* in_sizes, int n_in,
                              void* d_out, int out_size)
{
    const float* x      = (const float*)d_in[0];
    const int*   y      = (const int*)  d_in[1];
    const int*   seg    = (const int*)  d_in[2];
    const float* W_i    = (const float*)d_in[3];
    const float* b_i    = (const float*)d_in[4];
    const float* W_h    = (const float*)d_in[5];
    const float* b_h    = (const float*)d_in[6];
    const float* W_z    = (const float*)d_in[7];
    const float* b_z    = (const float*)d_in[8];
    const float* protos = (const float*)d_in[9];
    const float* W_clf  = (const float*)d_in[10];

    const int N = in_sizes[0] / IN_DIM;

    __half *h1, *w1p, *w2p, *wzp;
    float* z;
    cudaGetSymbolAddress((void**)&h1,  g_h1);
    cudaGetSymbolAddress((void**)&z,   g_z);
    cudaGetSymbolAddress((void**)&w1p, g_w1p);
    cudaGetSymbolAddress((void**)&w2p, g_w2p);
    cudaGetSymbolAddress((void**)&wzp, g_wzp);

    cudaFuncSetAttribute(gemm1_kernel, cudaFuncAttributeMaxDynamicSharedMemorySize, G1_SMEM);
    cudaFuncSetAttribute(gemm2_kernel, cudaFuncAttributeMaxDynamicSharedMemorySize, SMEM2);

    zero_accum_kernel<<<1, 512>>>();
    pack_w_kernel<<<(256 * KP1) / 256, 256>>>(W_i, w1p, IN_DIM, KP1, 256);
    pack_w_kernel<<<(256 * HD)  / 256, 256>>>(W_h, w2p, HD, HD, 256);
    pack_w_kernel<<<(ZD * HD)   / 256, 256>>>(W_z, wzp, HD, HD, ZD);

    gemm1_kernel<<<MBLK, 512, G1_SMEM>>>(x, w1p, b_i, h1, N);
    gemm2_kernel<<<MBLK, 512, SMEM2>>>(h1, w2p, b_h, wzp, b_z, z);

    head_kernel<<<(N + 255) / 256, 256>>>(z, seg, protos, W_clf, N);
    finalize_kernel<<<1, NB>>>(y, (float*)d_out, out_size);
}